// round 1
// baseline (speedup 1.0000x reference)
#include <cuda_runtime.h>
#include <cuda_bf16.h>
#include <math.h>

// Problem constants
#define B_  8
#define T_  1024
#define D_  512
#define H_  8
#define HD_ 64
#define DFF_ 1024
#define DPR_ 32
#define ROWS_ (B_*T_)   // 8192

// ---------------- scratch (device globals; no allocation allowed) ----------------
__device__ float g_h   [ROWS_*D_];        // ln1 output
__device__ float g_qkv [ROWS_*3*D_];      // qkv projection
__device__ float g_q   [B_*H_*T_*HD_];    // [B,H,T,HD]
__device__ float g_k   [B_*H_*T_*HD_];
__device__ float g_v   [B_*H_*T_*HD_];
__device__ float g_ao  [B_*H_*T_*HD_];    // attention out [B,H,T,HD]
__device__ float g_xres[ROWS_*D_];        // x_value + attn
__device__ float g_h2  [ROWS_*D_];        // ln2 output
__device__ float g_z   [ROWS_*2*DFF_];    // ffn1 raw
__device__ float g_g   [ROWS_*DFF_];      // swiglu output

// ---------------- block reduce helper (128 threads) ----------------
__device__ __forceinline__ void blockReduce2_128(float& a, float& b) {
    #pragma unroll
    for (int o = 16; o > 0; o >>= 1) {
        a += __shfl_xor_sync(0xffffffffu, a, o);
        b += __shfl_xor_sync(0xffffffffu, b, o);
    }
    __shared__ float sa[4], sb[4];
    int w = threadIdx.x >> 5;
    if ((threadIdx.x & 31) == 0) { sa[w] = a; sb[w] = b; }
    __syncthreads();
    a = sa[0] + sa[1] + sa[2] + sa[3];
    b = sb[0] + sb[1] + sb[2] + sb[3];
}

// ---------------- LayerNorm (row = 512 floats, 128 threads, float4) ----------------
__global__ void ln_kernel(const float* __restrict__ x,
                          const float* __restrict__ g,
                          const float* __restrict__ bta,
                          float* __restrict__ out) {
    int row = blockIdx.x;
    int tid = threadIdx.x;
    const float4* xr = (const float4*)(x + (size_t)row * D_);
    float4 v = xr[tid];
    float s  = v.x + v.y + v.z + v.w;
    float sq = v.x*v.x + v.y*v.y + v.z*v.z + v.w*v.w;
    blockReduce2_128(s, sq);
    float mean = s * (1.0f / D_);
    float var  = sq * (1.0f / D_) - mean * mean;
    float inv  = rsqrtf(var + 1e-5f);
    float4 gg = ((const float4*)g)[tid];
    float4 bb = ((const float4*)bta)[tid];
    float4 o;
    o.x = (v.x - mean) * inv * gg.x + bb.x;
    o.y = (v.y - mean) * inv * gg.y + bb.y;
    o.z = (v.z - mean) * inv * gg.z + bb.z;
    o.w = (v.w - mean) * inv * gg.w + bb.w;
    ((float4*)(out + (size_t)row * D_))[tid] = o;
}

// ---------------- residual add + LayerNorm2 (gathers heads) ----------------
__global__ void addres_ln2_kernel(const float* __restrict__ xv,
                                  const float* __restrict__ ao,
                                  const float* __restrict__ g,
                                  const float* __restrict__ bta,
                                  float* __restrict__ xres,
                                  float* __restrict__ h2) {
    int row = blockIdx.x;          // b*T + t
    int b = row >> 10;
    int t = row & (T_ - 1);
    int tid = threadIdx.x;         // 0..127, handles dims 4*tid..4*tid+3
    int d  = tid * 4;
    int h  = d >> 6;
    int dl = d & 63;
    float4 a = *(const float4*)(ao + ((((size_t)(b * H_ + h)) * T_ + t) * HD_ + dl));
    float4 v = ((const float4*)(xv + (size_t)row * D_))[tid];
    v.x += a.x; v.y += a.y; v.z += a.z; v.w += a.w;
    ((float4*)(xres + (size_t)row * D_))[tid] = v;
    float s  = v.x + v.y + v.z + v.w;
    float sq = v.x*v.x + v.y*v.y + v.z*v.z + v.w*v.w;
    blockReduce2_128(s, sq);
    float mean = s * (1.0f / D_);
    float var  = sq * (1.0f / D_) - mean * mean;
    float inv  = rsqrtf(var + 1e-5f);
    float4 gg = ((const float4*)g)[tid];
    float4 bb = ((const float4*)bta)[tid];
    float4 o;
    o.x = (v.x - mean) * inv * gg.x + bb.x;
    o.y = (v.y - mean) * inv * gg.y + bb.y;
    o.z = (v.z - mean) * inv * gg.z + bb.z;
    o.w = (v.w - mean) * inv * gg.w + bb.w;
    ((float4*)(h2 + (size_t)row * D_))[tid] = o;
}

// ---------------- SGEMM: C[M,N] = A[M,K] @ B[K,N] (+bias) (+res) ----------------
template<bool HAS_BIAS, bool HAS_RES>
__global__ __launch_bounds__(256)
void sgemm_kernel(const float* __restrict__ A, const float* __restrict__ Bm,
                  const float* __restrict__ bias, const float* __restrict__ res,
                  float* __restrict__ C, int M, int N, int K) {
    constexpr int BM = 128, BN = 128, BK = 8, TM = 8, TN = 8;
    __shared__ float As[BK][BM];
    __shared__ float Bs[BK][BN];
    int tid = threadIdx.x;
    int bx = blockIdx.x;   // N tiles
    int by = blockIdx.y;   // M tiles
    const float* Ab = A + (size_t)by * BM * K;
    const float* Bb = Bm + (size_t)bx * BN;
    int aRow = tid >> 1;
    int aCol = (tid & 1) * 4;
    int bRow = tid >> 5;
    int bCol = (tid & 31) * 4;
    int ty = tid >> 4;
    int tx = tid & 15;
    float acc[TM][TN];
    #pragma unroll
    for (int i = 0; i < TM; i++)
        #pragma unroll
        for (int j = 0; j < TN; j++) acc[i][j] = 0.f;

    for (int k0 = 0; k0 < K; k0 += BK) {
        float4 a4 = *(const float4*)(Ab + (size_t)aRow * K + k0 + aCol);
        As[aCol + 0][aRow] = a4.x;
        As[aCol + 1][aRow] = a4.y;
        As[aCol + 2][aRow] = a4.z;
        As[aCol + 3][aRow] = a4.w;
        float4 b4 = *(const float4*)(Bb + (size_t)(k0 + bRow) * N + bCol);
        *(float4*)(&Bs[bRow][bCol]) = b4;
        __syncthreads();
        #pragma unroll
        for (int k = 0; k < BK; k++) {
            float ra[TM], rb[TN];
            float4 a0 = *(const float4*)(&As[k][ty * TM]);
            float4 a1 = *(const float4*)(&As[k][ty * TM + 4]);
            ra[0]=a0.x; ra[1]=a0.y; ra[2]=a0.z; ra[3]=a0.w;
            ra[4]=a1.x; ra[5]=a1.y; ra[6]=a1.z; ra[7]=a1.w;
            float4 b0 = *(const float4*)(&Bs[k][tx * TN]);
            float4 b1 = *(const float4*)(&Bs[k][tx * TN + 4]);
            rb[0]=b0.x; rb[1]=b0.y; rb[2]=b0.z; rb[3]=b0.w;
            rb[4]=b1.x; rb[5]=b1.y; rb[6]=b1.z; rb[7]=b1.w;
            #pragma unroll
            for (int i = 0; i < TM; i++)
                #pragma unroll
                for (int j = 0; j < TN; j++)
                    acc[i][j] += ra[i] * rb[j];
        }
        __syncthreads();
    }

    int mBase = by * BM + ty * TM;
    int nBase = bx * BN + tx * TN;
    #pragma unroll
    for (int i = 0; i < TM; i++) {
        #pragma unroll
        for (int j = 0; j < TN; j += 4) {
            float4 v;
            v.x = acc[i][j + 0]; v.y = acc[i][j + 1];
            v.z = acc[i][j + 2]; v.w = acc[i][j + 3];
            if (HAS_BIAS) {
                float4 bb = *(const float4*)(bias + nBase + j);
                v.x += bb.x; v.y += bb.y; v.z += bb.z; v.w += bb.w;
            }
            if (HAS_RES) {
                float4 rr = *(const float4*)(res + (size_t)(mBase + i) * N + nBase + j);
                v.x += rr.x; v.y += rr.y; v.z += rr.z; v.w += rr.w;
            }
            *(float4*)(C + (size_t)(mBase + i) * N + nBase + j) = v;
        }
    }
}

// ---------------- QKV epilogue: type-emb add, RoPE, transpose to [B,H,T,HD] ----------------
__global__ void qkv_post_kernel(const float* __restrict__ qkv,
                                const int*   __restrict__ x_type,
                                const float* __restrict__ type_emb,
                                const float* __restrict__ seq_order,
                                float* __restrict__ Q, float* __restrict__ Ko,
                                float* __restrict__ V) {
    int row = blockIdx.x;       // b*T + t
    int b = row >> 10;
    int t = row & (T_ - 1);
    int p = threadIdx.x;        // 0..255 -> dim pair (2p, 2p+1)
    int d2 = 2 * p;

    int tq = x_type[b * (T_ + 1) + t];
    int tk = x_type[b * (T_ + 1) + t + 1];
    float pq = seq_order[b * (T_ + 1) + t];
    float pk = seq_order[b * (T_ + 1) + t + 1];

    const float* qr = qkv + (size_t)row * (3 * D_);
    float q0 = qr[d2]           + type_emb[(size_t)tq * (2 * D_) + d2];
    float q1 = qr[d2 + 1]       + type_emb[(size_t)tq * (2 * D_) + d2 + 1];
    float k0 = qr[D_ + d2]      + type_emb[(size_t)tk * (2 * D_) + D_ + d2];
    float k1 = qr[D_ + d2 + 1]  + type_emb[(size_t)tk * (2 * D_) + D_ + d2 + 1];
    float v0 = qr[2 * D_ + d2];
    float v1 = qr[2 * D_ + d2 + 1];

    int h  = d2 >> 6;
    int dl = d2 & 63;
    if (dl < DPR_) {
        // inv_freq = THETA^(-dl/DPR), interleaved rotation
        float f = powf(10000.0f, -(float)dl / (float)DPR_);
        float sq_, cq_, sk_, ck_;
        sincosf(pq * f, &sq_, &cq_);
        sincosf(pk * f, &sk_, &ck_);
        float nq0 = q0 * cq_ - q1 * sq_;
        float nq1 = q1 * cq_ + q0 * sq_;
        float nk0 = k0 * ck_ - k1 * sk_;
        float nk1 = k1 * ck_ + k0 * sk_;
        q0 = nq0; q1 = nq1; k0 = nk0; k1 = nk1;
    }
    size_t o = (((size_t)(b * H_ + h)) * T_ + t) * HD_ + dl;
    Q[o] = q0; Q[o + 1] = q1;
    Ko[o] = k0; Ko[o + 1] = k1;
    V[o] = v0; V[o + 1] = v1;
}

// ---------------- Flash attention (fp32, 1 query/thread, 64-key tiles) ----------------
__global__ __launch_bounds__(128)
void attn_kernel(const float* __restrict__ Q, const float* __restrict__ Kc,
                 const float* __restrict__ V, float* __restrict__ O) {
    constexpr int QT = 128, KT = 64;
    __shared__ float Ks[KT][HD_];
    __shared__ float Vs[KT][HD_];
    int qt = blockIdx.x;
    int h  = blockIdx.y;
    int b  = blockIdx.z;
    int tid = threadIdx.x;
    int q = qt * QT + tid;
    size_t head_base = ((size_t)(b * H_ + h)) * T_ * HD_;

    float qreg[HD_];
    {
        const float4* qp = (const float4*)(Q + head_base + (size_t)q * HD_);
        #pragma unroll
        for (int i = 0; i < 16; i++) {
            float4 tq = qp[i];
            qreg[4*i+0] = tq.x * 0.125f;
            qreg[4*i+1] = tq.y * 0.125f;
            qreg[4*i+2] = tq.z * 0.125f;
            qreg[4*i+3] = tq.w * 0.125f;
        }
    }
    float m = -1e30f, l = 0.f;
    float o[HD_];
    #pragma unroll
    for (int i = 0; i < HD_; i++) o[i] = 0.f;

    int nTiles = qt * 2 + 2;   // keys up to qt*128+127
    for (int kt = 0; kt < nTiles; kt++) {
        int j0 = kt * KT;
        const float4* kp = (const float4*)(Kc + head_base + (size_t)j0 * HD_);
        const float4* vp = (const float4*)(V  + head_base + (size_t)j0 * HD_);
        #pragma unroll
        for (int i = 0; i < 8; i++) {
            int idx = i * 128 + tid;
            ((float4*)Ks)[idx] = kp[idx];
            ((float4*)Vs)[idx] = vp[idx];
        }
        __syncthreads();

        for (int jc = 0; jc < KT; jc += 8) {
            if (j0 + jc > q) break;   // remaining keys all masked
            float s[8];
            #pragma unroll
            for (int jj = 0; jj < 8; jj++) {
                const float4* krow = (const float4*)(&Ks[jc + jj][0]);
                float a0 = 0.f, a1 = 0.f, a2 = 0.f, a3 = 0.f;
                #pragma unroll
                for (int i = 0; i < 16; i++) {
                    float4 kk = krow[i];
                    a0 += qreg[4*i+0] * kk.x;
                    a1 += qreg[4*i+1] * kk.y;
                    a2 += qreg[4*i+2] * kk.z;
                    a3 += qreg[4*i+3] * kk.w;
                }
                float sv = (a0 + a1) + (a2 + a3);
                int j = j0 + jc + jj;
                s[jj] = (j <= q) ? sv : -1e30f;
            }
            float cmax = s[0];
            #pragma unroll
            for (int jj = 1; jj < 8; jj++) cmax = fmaxf(cmax, s[jj]);
            if (cmax > m) {
                float scale = __expf(m - cmax);
                m = cmax;
                l *= scale;
                #pragma unroll
                for (int i = 0; i < HD_; i++) o[i] *= scale;
            }
            #pragma unroll
            for (int jj = 0; jj < 8; jj++) {
                float p = __expf(s[jj] - m);
                l += p;
                const float4* vrow = (const float4*)(&Vs[jc + jj][0]);
                #pragma unroll
                for (int i = 0; i < 16; i++) {
                    float4 vv = vrow[i];
                    o[4*i+0] += p * vv.x;
                    o[4*i+1] += p * vv.y;
                    o[4*i+2] += p * vv.z;
                    o[4*i+3] += p * vv.w;
                }
            }
        }
        __syncthreads();
    }

    float inv = 1.0f / l;
    float4* op = (float4*)(O + head_base + (size_t)q * HD_);
    #pragma unroll
    for (int i = 0; i < 16; i++) {
        float4 v;
        v.x = o[4*i+0] * inv; v.y = o[4*i+1] * inv;
        v.z = o[4*i+2] * inv; v.w = o[4*i+3] * inv;
        op[i] = v;
    }
}

// ---------------- SwiGLU: g = silu(z[:,DFF:]) * z[:,:DFF] ----------------
__global__ void swiglu_kernel(const float* __restrict__ z, float* __restrict__ g) {
    int idx = blockIdx.x * blockDim.x + threadIdx.x;   // over ROWS_*DFF_/4 float4
    int row = idx >> 8;          // 256 float4 per row
    int j4  = idx & 255;
    const float4* zr = (const float4*)(z + (size_t)row * (2 * DFF_));
    float4 a  = zr[j4];
    float4 gt = zr[j4 + DFF_ / 4];
    float4 r;
    r.x = a.x * (gt.x / (1.f + __expf(-gt.x)));
    r.y = a.y * (gt.y / (1.f + __expf(-gt.y)));
    r.z = a.z * (gt.z / (1.f + __expf(-gt.z)));
    r.w = a.w * (gt.w / (1.f + __expf(-gt.w)));
    ((float4*)(g + (size_t)row * DFF_))[j4] = r;
}

// ---------------- launch ----------------
extern "C" void kernel_launch(void* const* d_in, const int* in_sizes, int n_in,
                              void* d_out, int out_size) {
    (void)in_sizes; (void)n_in; (void)out_size;
    const int*   x_type   = (const int*)  d_in[0];
    const float* x_value  = (const float*)d_in[1];
    const float* seq_ord  = (const float*)d_in[2];
    const float* W_attn   = (const float*)d_in[3];
    const float* type_emb = (const float*)d_in[4];
    const float* ln1_g    = (const float*)d_in[5];
    const float* ln1_b    = (const float*)d_in[6];
    const float* ln2_g    = (const float*)d_in[7];
    const float* ln2_b    = (const float*)d_in[8];
    const float* W1       = (const float*)d_in[9];
    const float* b1       = (const float*)d_in[10];
    const float* W2       = (const float*)d_in[11];
    const float* b2       = (const float*)d_in[12];
    float* out = (float*)d_out;

    float *p_h, *p_qkv, *p_q, *p_k, *p_v, *p_ao, *p_xres, *p_h2, *p_z, *p_g;
    cudaGetSymbolAddress((void**)&p_h,    g_h);
    cudaGetSymbolAddress((void**)&p_qkv,  g_qkv);
    cudaGetSymbolAddress((void**)&p_q,    g_q);
    cudaGetSymbolAddress((void**)&p_k,    g_k);
    cudaGetSymbolAddress((void**)&p_v,    g_v);
    cudaGetSymbolAddress((void**)&p_ao,   g_ao);
    cudaGetSymbolAddress((void**)&p_xres, g_xres);
    cudaGetSymbolAddress((void**)&p_h2,   g_h2);
    cudaGetSymbolAddress((void**)&p_z,    g_z);
    cudaGetSymbolAddress((void**)&p_g,    g_g);

    // 1. LN1
    ln_kernel<<<ROWS_, 128>>>(x_value, ln1_g, ln1_b, p_h);
    // 2. QKV GEMM: [8192,512] @ [512,1536]
    sgemm_kernel<false, false><<<dim3(1536 / 128, ROWS_ / 128), 256>>>(
        p_h, W_attn, nullptr, nullptr, p_qkv, ROWS_, 3 * D_, D_);
    // 3. emb + RoPE + transpose
    qkv_post_kernel<<<ROWS_, 256>>>(p_qkv, x_type, type_emb, seq_ord, p_q, p_k, p_v);
    // 4. causal flash attention
    attn_kernel<<<dim3(T_ / 128, H_, B_), 128>>>(p_q, p_k, p_v, p_ao);
    // 5. residual + LN2
    addres_ln2_kernel<<<ROWS_, 128>>>(x_value, p_ao, ln2_g, ln2_b, p_xres, p_h2);
    // 6. FFN GEMM1: [8192,512] @ [512,2048] + b1
    sgemm_kernel<true, false><<<dim3(2 * DFF_ / 128, ROWS_ / 128), 256>>>(
        p_h2, W1, b1, nullptr, p_z, ROWS_, 2 * DFF_, D_);
    // 7. SwiGLU
    swiglu_kernel<<<(ROWS_ * DFF_ / 4) / 256, 256>>>(p_z, p_g);
    // 8. FFN GEMM2: [8192,1024] @ [1024,512] + b2 + residual -> out
    sgemm_kernel<true, true><<<dim3(D_ / 128, ROWS_ / 128), 256>>>(
        p_g, W2, b2, p_xres, out, ROWS_, D_, DFF_);
}

// round 2
// speedup vs baseline: 1.0190x; 1.0190x over previous
#include <cuda_runtime.h>
#include <cuda_bf16.h>
#include <math.h>

// Problem constants
#define B_  8
#define T_  1024
#define D_  512
#define H_  8
#define HD_ 64
#define DFF_ 1024
#define DPR_ 32
#define ROWS_ (B_*T_)   // 8192

// ---------------- scratch (device globals; no allocation allowed) ----------------
__device__ float g_h   [ROWS_*D_];        // ln1 output
__device__ float g_qkv [ROWS_*3*D_];      // qkv projection
__device__ float g_q   [B_*H_*T_*HD_];    // [B,H,T,HD]
__device__ float g_k   [B_*H_*T_*HD_];
__device__ float g_v   [B_*H_*T_*HD_];
__device__ float g_ao  [B_*H_*T_*HD_];    // attention out [B,H,T,HD]
__device__ float g_xres[ROWS_*D_];        // x_value + attn
__device__ float g_h2  [ROWS_*D_];        // ln2 output
__device__ float g_z   [ROWS_*2*DFF_];    // ffn1 raw
__device__ float g_g   [ROWS_*DFF_];      // swiglu output

// ---------------- helpers ----------------
__device__ __forceinline__ unsigned f2tf(float f) {
    unsigned u;
    asm("cvt.rna.tf32.f32 %0, %1;" : "=r"(u) : "f"(f));
    return u;
}

__device__ __forceinline__ void blockReduce2_128(float& a, float& b) {
    #pragma unroll
    for (int o = 16; o > 0; o >>= 1) {
        a += __shfl_xor_sync(0xffffffffu, a, o);
        b += __shfl_xor_sync(0xffffffffu, b, o);
    }
    __shared__ float sa[4], sb[4];
    int w = threadIdx.x >> 5;
    if ((threadIdx.x & 31) == 0) { sa[w] = a; sb[w] = b; }
    __syncthreads();
    a = sa[0] + sa[1] + sa[2] + sa[3];
    b = sb[0] + sb[1] + sb[2] + sb[3];
}

// ---------------- LayerNorm (row = 512 floats, 128 threads, float4) ----------------
__global__ void ln_kernel(const float* __restrict__ x,
                          const float* __restrict__ g,
                          const float* __restrict__ bta,
                          float* __restrict__ out) {
    int row = blockIdx.x;
    int tid = threadIdx.x;
    const float4* xr = (const float4*)(x + (size_t)row * D_);
    float4 v = xr[tid];
    float s  = v.x + v.y + v.z + v.w;
    float sq = v.x*v.x + v.y*v.y + v.z*v.z + v.w*v.w;
    blockReduce2_128(s, sq);
    float mean = s * (1.0f / D_);
    float var  = sq * (1.0f / D_) - mean * mean;
    float inv  = rsqrtf(var + 1e-5f);
    float4 gg = ((const float4*)g)[tid];
    float4 bb = ((const float4*)bta)[tid];
    float4 o;
    o.x = (v.x - mean) * inv * gg.x + bb.x;
    o.y = (v.y - mean) * inv * gg.y + bb.y;
    o.z = (v.z - mean) * inv * gg.z + bb.z;
    o.w = (v.w - mean) * inv * gg.w + bb.w;
    ((float4*)(out + (size_t)row * D_))[tid] = o;
}

// ---------------- residual add + LayerNorm2 (gathers heads) ----------------
__global__ void addres_ln2_kernel(const float* __restrict__ xv,
                                  const float* __restrict__ ao,
                                  const float* __restrict__ g,
                                  const float* __restrict__ bta,
                                  float* __restrict__ xres,
                                  float* __restrict__ h2) {
    int row = blockIdx.x;          // b*T + t
    int b = row >> 10;
    int t = row & (T_ - 1);
    int tid = threadIdx.x;         // 0..127, handles dims 4*tid..4*tid+3
    int d  = tid * 4;
    int h  = d >> 6;
    int dl = d & 63;
    float4 a = *(const float4*)(ao + ((((size_t)(b * H_ + h)) * T_ + t) * HD_ + dl));
    float4 v = ((const float4*)(xv + (size_t)row * D_))[tid];
    v.x += a.x; v.y += a.y; v.z += a.z; v.w += a.w;
    ((float4*)(xres + (size_t)row * D_))[tid] = v;
    float s  = v.x + v.y + v.z + v.w;
    float sq = v.x*v.x + v.y*v.y + v.z*v.z + v.w*v.w;
    blockReduce2_128(s, sq);
    float mean = s * (1.0f / D_);
    float var  = sq * (1.0f / D_) - mean * mean;
    float inv  = rsqrtf(var + 1e-5f);
    float4 gg = ((const float4*)g)[tid];
    float4 bb = ((const float4*)bta)[tid];
    float4 o;
    o.x = (v.x - mean) * inv * gg.x + bb.x;
    o.y = (v.y - mean) * inv * gg.y + bb.y;
    o.z = (v.z - mean) * inv * gg.z + bb.z;
    o.w = (v.w - mean) * inv * gg.w + bb.w;
    ((float4*)(h2 + (size_t)row * D_))[tid] = o;
}

// ================= tf32 tensor-core GEMM =================
// C[M,N] = A[M,K] @ B[K,N] (+bias) (+res), row-major, tf32 mma m16n8k8.
// BM=128, BN=128, BK=32, 256 threads (8 warps, warp tile 64x32),
// double-buffered smem in fragment-permuted layout:
//   A frag block (mt,ks): 32 lanes x 4 regs contiguous -> LDS.128
//   B frag block (nt,ks): 32 lanes x 2 regs contiguous -> LDS.64
template<bool HAS_BIAS, bool HAS_RES>
__global__ __launch_bounds__(256)
void tf32_gemm(const float* __restrict__ A, const float* __restrict__ Bm,
               const float* __restrict__ bias, const float* __restrict__ res,
               float* __restrict__ C, int M, int N, int K) {
    extern __shared__ unsigned smem[];   // 2 stages x (4096 A + 4096 B) words = 64KB
    const int t = threadIdx.x;
    const int m0 = blockIdx.y * 128;
    const int n0 = blockIdx.x * 128;
    const int warp = t >> 5, lane = t & 31;
    const int wm = (warp >> 2) * 64;     // warp row offset in tile
    const int wn = (warp & 3) * 32;      // warp col offset in tile
    const int g  = lane >> 2, tig = lane & 3;

    float acc[4][4][4];
    #pragma unroll
    for (int i = 0; i < 4; i++)
        #pragma unroll
        for (int j = 0; j < 4; j++)
            #pragma unroll
            for (int e = 0; e < 4; e++) acc[i][j][e] = 0.f;

    unsigned av[4][4], bv[4][4];

    // prefetch tile 0
    #pragma unroll
    for (int j = 0; j < 4; j++) {
        int i = t + 256 * j;
        float4 va = *(const float4*)(A + (size_t)(m0 + (i >> 3)) * K + (i & 7) * 4);
        av[j][0] = f2tf(va.x); av[j][1] = f2tf(va.y);
        av[j][2] = f2tf(va.z); av[j][3] = f2tf(va.w);
        float4 vb = *(const float4*)(Bm + (size_t)(i >> 5) * N + n0 + (i & 31) * 4);
        bv[j][0] = f2tf(vb.x); bv[j][1] = f2tf(vb.y);
        bv[j][2] = f2tf(vb.z); bv[j][3] = f2tf(vb.w);
    }

    const int nIter = K >> 5;
    int buf = 0;
    for (int it = 0; it < nIter; ++it) {
        unsigned* As = smem + buf * 8192;
        unsigned* Bs = As + 4096;
        // ---- store prefetched regs to fragment-permuted smem ----
        #pragma unroll
        for (int j = 0; j < 4; j++) {
            int i = t + 256 * j;
            {   // A: mA = i>>3 (0..127), k4 = i&7 (cols k4*4..+3)
                int mA = i >> 3, k4 = i & 7;
                int mt = mA >> 4, r = mA & 15;
                int ks = k4 >> 1;
                int regb = (r >> 3) + ((k4 & 1) << 1);
                unsigned base = ((mt * 4 + ks) * 32 + (r & 7) * 4) * 4 + regb;
                As[base + 0] = av[j][0];
                As[base + 4] = av[j][1];
                As[base + 8] = av[j][2];
                As[base + 12] = av[j][3];
            }
            {   // B: kB = i>>5 (0..31), n4 = i&31 (cols n4*4..+3)
                int kB = i >> 5, n4 = i & 31;
                int ks = kB >> 3, r8 = kB & 7;
                int regb = r8 >> 2;
                unsigned base = (((n4 >> 1) * 4 + ks) * 32 + (n4 & 1) * 16 + (r8 & 3)) * 2 + regb;
                Bs[base + 0] = bv[j][0];
                Bs[base + 8] = bv[j][1];
                Bs[base + 16] = bv[j][2];
                Bs[base + 24] = bv[j][3];
            }
        }
        __syncthreads();
        // ---- prefetch next tile ----
        if (it + 1 < nIter) {
            int k0 = (it + 1) << 5;
            #pragma unroll
            for (int j = 0; j < 4; j++) {
                int i = t + 256 * j;
                float4 va = *(const float4*)(A + (size_t)(m0 + (i >> 3)) * K + k0 + (i & 7) * 4);
                av[j][0] = f2tf(va.x); av[j][1] = f2tf(va.y);
                av[j][2] = f2tf(va.z); av[j][3] = f2tf(va.w);
                float4 vb = *(const float4*)(Bm + (size_t)(k0 + (i >> 5)) * N + n0 + (i & 31) * 4);
                bv[j][0] = f2tf(vb.x); bv[j][1] = f2tf(vb.y);
                bv[j][2] = f2tf(vb.z); bv[j][3] = f2tf(vb.w);
            }
        }
        // ---- compute from smem ----
        #pragma unroll
        for (int ks = 0; ks < 4; ks++) {
            unsigned a[4][4], b[4][2];
            #pragma unroll
            for (int mt = 0; mt < 4; mt++) {
                int mtg = (wm >> 4) + mt;
                uint4 q = *(const uint4*)(As + ((mtg * 4 + ks) * 32 + lane) * 4);
                a[mt][0] = q.x; a[mt][1] = q.y; a[mt][2] = q.z; a[mt][3] = q.w;
            }
            #pragma unroll
            for (int nt = 0; nt < 4; nt++) {
                int ntg = (wn >> 3) + nt;
                uint2 q = *(const uint2*)(Bs + ((ntg * 4 + ks) * 32 + lane) * 2);
                b[nt][0] = q.x; b[nt][1] = q.y;
            }
            #pragma unroll
            for (int mt = 0; mt < 4; mt++)
                #pragma unroll
                for (int nt = 0; nt < 4; nt++) {
                    asm volatile(
                        "mma.sync.aligned.m16n8k8.row.col.f32.tf32.tf32.f32 "
                        "{%0,%1,%2,%3}, {%4,%5,%6,%7}, {%8,%9}, {%0,%1,%2,%3};"
                        : "+f"(acc[mt][nt][0]), "+f"(acc[mt][nt][1]),
                          "+f"(acc[mt][nt][2]), "+f"(acc[mt][nt][3])
                        : "r"(a[mt][0]), "r"(a[mt][1]), "r"(a[mt][2]), "r"(a[mt][3]),
                          "r"(b[nt][0]), "r"(b[nt][1]));
                }
        }
        buf ^= 1;
        // note: next iteration's store targets the buffer last *read* two
        // iterations ago; the single __syncthreads above is sufficient.
    }

    // ---- epilogue ----
    #pragma unroll
    for (int mt = 0; mt < 4; mt++) {
        int row0 = m0 + wm + mt * 16 + g;
        #pragma unroll
        for (int nt = 0; nt < 4; nt++) {
            int col = n0 + wn + nt * 8 + tig * 2;
            float2 v0 = make_float2(acc[mt][nt][0], acc[mt][nt][1]);   // row0
            float2 v1 = make_float2(acc[mt][nt][2], acc[mt][nt][3]);   // row0+8
            if (HAS_BIAS) {
                float2 bb = *(const float2*)(bias + col);
                v0.x += bb.x; v0.y += bb.y; v1.x += bb.x; v1.y += bb.y;
            }
            if (HAS_RES) {
                float2 r0 = *(const float2*)(res + (size_t)row0 * N + col);
                float2 r1 = *(const float2*)(res + (size_t)(row0 + 8) * N + col);
                v0.x += r0.x; v0.y += r0.y; v1.x += r1.x; v1.y += r1.y;
            }
            *(float2*)(C + (size_t)row0 * N + col) = v0;
            *(float2*)(C + (size_t)(row0 + 8) * N + col) = v1;
        }
    }
}

// ---------------- QKV epilogue: type-emb add, RoPE, transpose to [B,H,T,HD] ----------------
__global__ void qkv_post_kernel(const float* __restrict__ qkv,
                                const int*   __restrict__ x_type,
                                const float* __restrict__ type_emb,
                                const float* __restrict__ seq_order,
                                float* __restrict__ Q, float* __restrict__ Ko,
                                float* __restrict__ V) {
    int row = blockIdx.x;       // b*T + t
    int b = row >> 10;
    int t = row & (T_ - 1);
    int p = threadIdx.x;        // 0..255 -> dim pair (2p, 2p+1)
    int d2 = 2 * p;

    int tq = x_type[b * (T_ + 1) + t];
    int tk = x_type[b * (T_ + 1) + t + 1];
    float pq = seq_order[b * (T_ + 1) + t];
    float pk = seq_order[b * (T_ + 1) + t + 1];

    const float* qr = qkv + (size_t)row * (3 * D_);
    float q0 = qr[d2]           + type_emb[(size_t)tq * (2 * D_) + d2];
    float q1 = qr[d2 + 1]       + type_emb[(size_t)tq * (2 * D_) + d2 + 1];
    float k0 = qr[D_ + d2]      + type_emb[(size_t)tk * (2 * D_) + D_ + d2];
    float k1 = qr[D_ + d2 + 1]  + type_emb[(size_t)tk * (2 * D_) + D_ + d2 + 1];
    float v0 = qr[2 * D_ + d2];
    float v1 = qr[2 * D_ + d2 + 1];

    int h  = d2 >> 6;
    int dl = d2 & 63;
    if (dl < DPR_) {
        // inv_freq = 10000^(-dl/32) = exp2(dl * -log2(10000)/32)
        float f = exp2f((float)dl * (-13.287712379549449f / 32.0f));
        float sq_, cq_, sk_, ck_;
        sincosf(pq * f, &sq_, &cq_);
        sincosf(pk * f, &sk_, &ck_);
        float nq0 = q0 * cq_ - q1 * sq_;
        float nq1 = q1 * cq_ + q0 * sq_;
        float nk0 = k0 * ck_ - k1 * sk_;
        float nk1 = k1 * ck_ + k0 * sk_;
        q0 = nq0; q1 = nq1; k0 = nk0; k1 = nk1;
    }
    size_t o = (((size_t)(b * H_ + h)) * T_ + t) * HD_ + dl;
    Q[o] = q0; Q[o + 1] = q1;
    Ko[o] = k0; Ko[o + 1] = k1;
    V[o] = v0; V[o + 1] = v1;
}

// ---------------- Flash attention (fp32, 1 query/thread, 64-key tiles) ----------------
// Load balance: block `pair` handles q-tiles {pair, 7-pair} -> every block does
// exactly 18 key-tiles; grid 256 = one balanced wave at 2 CTAs/SM.
__global__ __launch_bounds__(128)
void attn_kernel(const float* __restrict__ Q, const float* __restrict__ Kc,
                 const float* __restrict__ V, float* __restrict__ O) {
    constexpr int QT = 128, KT = 64;
    __shared__ float Ks[KT][HD_];
    __shared__ float Vs[KT][HD_];
    int pair = blockIdx.x;     // 0..3
    int h  = blockIdx.y;
    int b  = blockIdx.z;
    int tid = threadIdx.x;
    size_t head_base = ((size_t)(b * H_ + h)) * T_ * HD_;

    #pragma unroll 1
    for (int rep = 0; rep < 2; rep++) {
        int qt = (rep == 0) ? pair : (7 - pair);
        int q = qt * QT + tid;

        float qreg[HD_];
        {
            const float4* qp = (const float4*)(Q + head_base + (size_t)q * HD_);
            #pragma unroll
            for (int i = 0; i < 16; i++) {
                float4 tq = qp[i];
                qreg[4*i+0] = tq.x * 0.125f;
                qreg[4*i+1] = tq.y * 0.125f;
                qreg[4*i+2] = tq.z * 0.125f;
                qreg[4*i+3] = tq.w * 0.125f;
            }
        }
        float m = -1e30f, l = 0.f;
        float o[HD_];
        #pragma unroll
        for (int i = 0; i < HD_; i++) o[i] = 0.f;

        int nTiles = qt * 2 + 2;   // keys up to qt*128+127
        for (int kt = 0; kt < nTiles; kt++) {
            int j0 = kt * KT;
            const float4* kp = (const float4*)(Kc + head_base + (size_t)j0 * HD_);
            const float4* vp = (const float4*)(V  + head_base + (size_t)j0 * HD_);
            #pragma unroll
            for (int i = 0; i < 8; i++) {
                int idx = i * 128 + tid;
                ((float4*)Ks)[idx] = kp[idx];
                ((float4*)Vs)[idx] = vp[idx];
            }
            __syncthreads();

            for (int jc = 0; jc < KT; jc += 8) {
                if (j0 + jc > q) break;   // remaining keys all masked
                float s[8];
                #pragma unroll
                for (int jj = 0; jj < 8; jj++) {
                    const float4* krow = (const float4*)(&Ks[jc + jj][0]);
                    float a0 = 0.f, a1 = 0.f, a2 = 0.f, a3 = 0.f;
                    #pragma unroll
                    for (int i = 0; i < 16; i++) {
                        float4 kk = krow[i];
                        a0 += qreg[4*i+0] * kk.x;
                        a1 += qreg[4*i+1] * kk.y;
                        a2 += qreg[4*i+2] * kk.z;
                        a3 += qreg[4*i+3] * kk.w;
                    }
                    float sv = (a0 + a1) + (a2 + a3);
                    int j = j0 + jc + jj;
                    s[jj] = (j <= q) ? sv : -1e30f;
                }
                float cmax = s[0];
                #pragma unroll
                for (int jj = 1; jj < 8; jj++) cmax = fmaxf(cmax, s[jj]);
                if (cmax > m) {
                    float scale = __expf(m - cmax);
                    m = cmax;
                    l *= scale;
                    #pragma unroll
                    for (int i = 0; i < HD_; i++) o[i] *= scale;
                }
                #pragma unroll
                for (int jj = 0; jj < 8; jj++) {
                    float p = __expf(s[jj] - m);
                    l += p;
                    const float4* vrow = (const float4*)(&Vs[jc + jj][0]);
                    #pragma unroll
                    for (int i = 0; i < 16; i++) {
                        float4 vv = vrow[i];
                        o[4*i+0] += p * vv.x;
                        o[4*i+1] += p * vv.y;
                        o[4*i+2] += p * vv.z;
                        o[4*i+3] += p * vv.w;
                    }
                }
            }
            __syncthreads();
        }

        float inv = 1.0f / l;
        float4* op = (float4*)(O + head_base + (size_t)q * HD_);
        #pragma unroll
        for (int i = 0; i < 16; i++) {
            float4 v;
            v.x = o[4*i+0] * inv; v.y = o[4*i+1] * inv;
            v.z = o[4*i+2] * inv; v.w = o[4*i+3] * inv;
            op[i] = v;
        }
    }
}

// ---------------- SwiGLU: g = silu(z[:,DFF:]) * z[:,:DFF] ----------------
__global__ void swiglu_kernel(const float* __restrict__ z, float* __restrict__ g) {
    int idx = blockIdx.x * blockDim.x + threadIdx.x;   // over ROWS_*DFF_/4 float4
    int row = idx >> 8;          // 256 float4 per row
    int j4  = idx & 255;
    const float4* zr = (const float4*)(z + (size_t)row * (2 * DFF_));
    float4 a  = zr[j4];
    float4 gt = zr[j4 + DFF_ / 4];
    float4 r;
    r.x = a.x * (gt.x / (1.f + __expf(-gt.x)));
    r.y = a.y * (gt.y / (1.f + __expf(-gt.y)));
    r.z = a.z * (gt.z / (1.f + __expf(-gt.z)));
    r.w = a.w * (gt.w / (1.f + __expf(-gt.w)));
    ((float4*)(g + (size_t)row * DFF_))[j4] = r;
}

// ---------------- launch ----------------
extern "C" void kernel_launch(void* const* d_in, const int* in_sizes, int n_in,
                              void* d_out, int out_size) {
    (void)in_sizes; (void)n_in; (void)out_size;
    const int*   x_type   = (const int*)  d_in[0];
    const float* x_value  = (const float*)d_in[1];
    const float* seq_ord  = (const float*)d_in[2];
    const float* W_attn   = (const float*)d_in[3];
    const float* type_emb = (const float*)d_in[4];
    const float* ln1_g    = (const float*)d_in[5];
    const float* ln1_b    = (const float*)d_in[6];
    const float* ln2_g    = (const float*)d_in[7];
    const float* ln2_b    = (const float*)d_in[8];
    const float* W1       = (const float*)d_in[9];
    const float* b1       = (const float*)d_in[10];
    const float* W2       = (const float*)d_in[11];
    const float* b2       = (const float*)d_in[12];
    float* out = (float*)d_out;

    float *p_h, *p_qkv, *p_q, *p_k, *p_v, *p_ao, *p_xres, *p_h2, *p_z, *p_g;
    cudaGetSymbolAddress((void**)&p_h,    g_h);
    cudaGetSymbolAddress((void**)&p_qkv,  g_qkv);
    cudaGetSymbolAddress((void**)&p_q,    g_q);
    cudaGetSymbolAddress((void**)&p_k,    g_k);
    cudaGetSymbolAddress((void**)&p_v,    g_v);
    cudaGetSymbolAddress((void**)&p_ao,   g_ao);
    cudaGetSymbolAddress((void**)&p_xres, g_xres);
    cudaGetSymbolAddress((void**)&p_h2,   g_h2);
    cudaGetSymbolAddress((void**)&p_z,    g_z);
    cudaGetSymbolAddress((void**)&p_g,    g_g);

    const int SMEM = 65536;   // 2-stage double buffer
    cudaFuncSetAttribute(tf32_gemm<false, false>,
                         cudaFuncAttributeMaxDynamicSharedMemorySize, SMEM);
    cudaFuncSetAttribute(tf32_gemm<true, false>,
                         cudaFuncAttributeMaxDynamicSharedMemorySize, SMEM);
    cudaFuncSetAttribute(tf32_gemm<true, true>,
                         cudaFuncAttributeMaxDynamicSharedMemorySize, SMEM);

    // 1. LN1
    ln_kernel<<<ROWS_, 128>>>(x_value, ln1_g, ln1_b, p_h);
    // 2. QKV GEMM: [8192,512] @ [512,1536]
    tf32_gemm<false, false><<<dim3(1536 / 128, ROWS_ / 128), 256, SMEM>>>(
        p_h, W_attn, nullptr, nullptr, p_qkv, ROWS_, 3 * D_, D_);
    // 3. emb + RoPE + transpose
    qkv_post_kernel<<<ROWS_, 256>>>(p_qkv, x_type, type_emb, seq_ord, p_q, p_k, p_v);
    // 4. causal flash attention (balanced q-tile pairs)
    attn_kernel<<<dim3(4, H_, B_), 128>>>(p_q, p_k, p_v, p_ao);
    // 5. residual + LN2
    addres_ln2_kernel<<<ROWS_, 128>>>(x_value, p_ao, ln2_g, ln2_b, p_xres, p_h2);
    // 6. FFN GEMM1: [8192,512] @ [512,2048] + b1
    tf32_gemm<true, false><<<dim3(2 * DFF_ / 128, ROWS_ / 128), 256, SMEM>>>(
        p_h2, W1, b1, nullptr, p_z, ROWS_, 2 * DFF_, D_);
    // 7. SwiGLU
    swiglu_kernel<<<(ROWS_ * DFF_ / 4) / 256, 256>>>(p_z, p_g);
    // 8. FFN GEMM2: [8192,1024] @ [1024,512] + b2 + residual -> out
    tf32_gemm<true, true><<<dim3(D_ / 128, ROWS_ / 128), 256, SMEM>>>(
        p_g, W2, b2, p_xres, out, ROWS_, D_, DFF_);
}

// round 4
// speedup vs baseline: 2.1904x; 2.1497x over previous
#include <cuda_runtime.h>
#include <cuda_bf16.h>
#include <math.h>

// Problem constants
#define B_  8
#define T_  1024
#define D_  512
#define H_  8
#define HD_ 64
#define DFF_ 1024
#define DPR_ 32
#define ROWS_ (B_*T_)   // 8192

// ---------------- scratch (device globals; no allocation allowed) ----------------
__device__ float g_h   [ROWS_*D_];        // ln1 output
__device__ float g_qkv [ROWS_*3*D_];      // qkv projection
__device__ float g_q   [B_*H_*T_*HD_];    // [B,H,T,HD]
__device__ float g_k   [B_*H_*T_*HD_];
__device__ float g_v   [B_*H_*T_*HD_];
__device__ float g_ao  [B_*H_*T_*HD_];    // attention out [B,H,T,HD]
__device__ float g_xres[ROWS_*D_];        // x_value + attn
__device__ float g_h2  [ROWS_*D_];        // ln2 output
__device__ float g_z   [ROWS_*2*DFF_];    // ffn1 raw
__device__ float g_g   [ROWS_*DFF_];      // swiglu output

// ---------------- helpers ----------------
__device__ __forceinline__ void cpasync16(unsigned s, const void* g) {
    asm volatile("cp.async.cg.shared.global [%0], [%1], 16;" :: "r"(s), "l"(g));
}
__device__ __forceinline__ void cpcommit() {
    asm volatile("cp.async.commit_group;");
}
__device__ __forceinline__ unsigned rna_tf32(unsigned u) {
    unsigned r;
    asm("cvt.rna.tf32.f32 %0, %1;" : "=r"(r) : "r"(u));
    return r;
}

__device__ __forceinline__ void blockReduce2_128(float& a, float& b) {
    #pragma unroll
    for (int o = 16; o > 0; o >>= 1) {
        a += __shfl_xor_sync(0xffffffffu, a, o);
        b += __shfl_xor_sync(0xffffffffu, b, o);
    }
    __shared__ float sa[4], sb[4];
    int w = threadIdx.x >> 5;
    if ((threadIdx.x & 31) == 0) { sa[w] = a; sb[w] = b; }
    __syncthreads();
    a = sa[0] + sa[1] + sa[2] + sa[3];
    b = sb[0] + sb[1] + sb[2] + sb[3];
}

// ---------------- LayerNorm (row = 512 floats, 128 threads, float4) ----------------
__global__ void ln_kernel(const float* __restrict__ x,
                          const float* __restrict__ g,
                          const float* __restrict__ bta,
                          float* __restrict__ out) {
    int row = blockIdx.x;
    int tid = threadIdx.x;
    const float4* xr = (const float4*)(x + (size_t)row * D_);
    float4 v = xr[tid];
    float s  = v.x + v.y + v.z + v.w;
    float sq = v.x*v.x + v.y*v.y + v.z*v.z + v.w*v.w;
    blockReduce2_128(s, sq);
    float mean = s * (1.0f / D_);
    float var  = sq * (1.0f / D_) - mean * mean;
    float inv  = rsqrtf(var + 1e-5f);
    float4 gg = ((const float4*)g)[tid];
    float4 bb = ((const float4*)bta)[tid];
    float4 o;
    o.x = (v.x - mean) * inv * gg.x + bb.x;
    o.y = (v.y - mean) * inv * gg.y + bb.y;
    o.z = (v.z - mean) * inv * gg.z + bb.z;
    o.w = (v.w - mean) * inv * gg.w + bb.w;
    ((float4*)(out + (size_t)row * D_))[tid] = o;
}

// ---------------- residual add + LayerNorm2 (gathers heads) ----------------
__global__ void addres_ln2_kernel(const float* __restrict__ xv,
                                  const float* __restrict__ ao,
                                  const float* __restrict__ g,
                                  const float* __restrict__ bta,
                                  float* __restrict__ xres,
                                  float* __restrict__ h2) {
    int row = blockIdx.x;          // b*T + t
    int b = row >> 10;
    int t = row & (T_ - 1);
    int tid = threadIdx.x;         // 0..127, handles dims 4*tid..4*tid+3
    int d  = tid * 4;
    int h  = d >> 6;
    int dl = d & 63;
    float4 a = *(const float4*)(ao + ((((size_t)(b * H_ + h)) * T_ + t) * HD_ + dl));
    float4 v = ((const float4*)(xv + (size_t)row * D_))[tid];
    v.x += a.x; v.y += a.y; v.z += a.z; v.w += a.w;
    ((float4*)(xres + (size_t)row * D_))[tid] = v;
    float s  = v.x + v.y + v.z + v.w;
    float sq = v.x*v.x + v.y*v.y + v.z*v.z + v.w*v.w;
    blockReduce2_128(s, sq);
    float mean = s * (1.0f / D_);
    float var  = sq * (1.0f / D_) - mean * mean;
    float inv  = rsqrtf(var + 1e-5f);
    float4 gg = ((const float4*)g)[tid];
    float4 bb = ((const float4*)bta)[tid];
    float4 o;
    o.x = (v.x - mean) * inv * gg.x + bb.x;
    o.y = (v.y - mean) * inv * gg.y + bb.y;
    o.z = (v.z - mean) * inv * gg.z + bb.z;
    o.w = (v.w - mean) * inv * gg.w + bb.w;
    ((float4*)(h2 + (size_t)row * D_))[tid] = o;
}

// ================= tf32 tensor-core GEMM (cp.async, conflict-free pads) ========
// C[M,N] = A[M,K] @ B[K,N] (+bias) (+res), row-major, mma m16n8k8 tf32.
// BM=128, BN=128, BK=32, 256 threads (8 warps, warp tile 64x32).
// smem per stage: A 128x36 words (pad 4) + B 32x136 words (pad 8).
//   A frag load bank = 4g+tig  -> 32 distinct (conflict-free)
//   B frag load bank = 8(l&3)+(l>>2) -> 32 distinct (conflict-free)
//   cp.async stores: consecutive lanes contiguous 16B -> conflict-free
// Fragments are rounded to tf32 with cvt.rna AFTER the smem load (register-side)
// so accumulation error stays unbiased (~2.7e-4), not truncation-biased.
#define ASTRIDE 36
#define BSTRIDE 136
#define STAGE_WORDS (128*ASTRIDE + 32*BSTRIDE)   // 4608 + 4352 = 8960
#define GSMEM_BYTES (2 * STAGE_WORDS * 4)        // 71680

template<bool HAS_BIAS, bool HAS_RES>
__global__ __launch_bounds__(256, 2)
void tf32_gemm(const float* __restrict__ A, const float* __restrict__ Bm,
               const float* __restrict__ bias, const float* __restrict__ res,
               float* __restrict__ C, int M, int N, int K) {
    extern __shared__ float smem[];
    const unsigned sbase = (unsigned)__cvta_generic_to_shared(smem);
    const int t = threadIdx.x;
    const int m0 = blockIdx.y * 128;
    const int n0 = blockIdx.x * 128;
    const int warp = t >> 5, lane = t & 31;
    const int wm = (warp >> 2) * 64;     // warp row offset in tile
    const int wn = (warp & 3) * 32;      // warp col offset in tile
    const int g  = lane >> 2, tig = lane & 3;

    float acc[4][4][4];
    #pragma unroll
    for (int i = 0; i < 4; i++)
        #pragma unroll
        for (int j = 0; j < 4; j++)
            #pragma unroll
            for (int e = 0; e < 4; e++) acc[i][j][e] = 0.f;

    const int mA = t >> 3, k4 = t & 7;     // A copy coords
    const int kB = t >> 5, n4 = t & 31;    // B copy coords

    // ---- issue stage 0 ----
    {
        unsigned sA = sbase;
        unsigned sB = sbase + 128*ASTRIDE*4;
        #pragma unroll
        for (int j = 0; j < 4; j++) {
            int ma = mA + 32*j;
            cpasync16(sA + (ma*ASTRIDE + k4*4)*4, A + (size_t)(m0 + ma)*K + k4*4);
            int kb = kB + 8*j;
            cpasync16(sB + (kb*BSTRIDE + n4*4)*4, Bm + (size_t)kb*N + n0 + n4*4);
        }
        cpcommit();
    }

    const int nIter = K >> 5;
    int buf = 0;
    for (int it = 0; it < nIter; ++it) {
        if (it + 1 < nIter) {
            int k0 = (it + 1) << 5;
            unsigned sA = sbase + (buf ^ 1) * STAGE_WORDS * 4;
            unsigned sB = sA + 128*ASTRIDE*4;
            #pragma unroll
            for (int j = 0; j < 4; j++) {
                int ma = mA + 32*j;
                cpasync16(sA + (ma*ASTRIDE + k4*4)*4,
                          A + (size_t)(m0 + ma)*K + k0 + k4*4);
                int kb = kB + 8*j;
                cpasync16(sB + (kb*BSTRIDE + n4*4)*4,
                          Bm + (size_t)(k0 + kb)*N + n0 + n4*4);
            }
            cpcommit();
            asm volatile("cp.async.wait_group 1;");
        } else {
            asm volatile("cp.async.wait_group 0;");
        }
        __syncthreads();

        const unsigned* Asu = (const unsigned*)(smem + buf * STAGE_WORDS);
        const unsigned* Bsu = Asu + 128*ASTRIDE;

        #pragma unroll
        for (int ks = 0; ks < 4; ks++) {
            unsigned a[4][2][2], b[4][2];
            #pragma unroll
            for (int mt = 0; mt < 4; mt++) {
                const unsigned* p = Asu + (wm + mt*16 + g)*ASTRIDE + ks*8 + tig;
                a[mt][0][0] = rna_tf32(p[0]);
                a[mt][1][0] = rna_tf32(p[8*ASTRIDE]);
                a[mt][0][1] = rna_tf32(p[4]);
                a[mt][1][1] = rna_tf32(p[8*ASTRIDE + 4]);
            }
            #pragma unroll
            for (int nt = 0; nt < 4; nt++) {
                const unsigned* p = Bsu + (ks*8 + (lane&3))*BSTRIDE
                                        + wn + nt*8 + (lane>>2);
                b[nt][0] = rna_tf32(p[0]);
                b[nt][1] = rna_tf32(p[4*BSTRIDE]);
            }
            #pragma unroll
            for (int mt = 0; mt < 4; mt++)
                #pragma unroll
                for (int nt = 0; nt < 4; nt++) {
                    asm volatile(
                        "mma.sync.aligned.m16n8k8.row.col.f32.tf32.tf32.f32 "
                        "{%0,%1,%2,%3}, {%4,%5,%6,%7}, {%8,%9}, {%0,%1,%2,%3};"
                        : "+f"(acc[mt][nt][0]), "+f"(acc[mt][nt][1]),
                          "+f"(acc[mt][nt][2]), "+f"(acc[mt][nt][3])
                        : "r"(a[mt][0][0]), "r"(a[mt][1][0]),
                          "r"(a[mt][0][1]), "r"(a[mt][1][1]),
                          "r"(b[nt][0]), "r"(b[nt][1]));
                }
        }
        __syncthreads();   // protect buf before next-iter cp.async overwrites it
        buf ^= 1;
    }

    // ---- epilogue ----
    #pragma unroll
    for (int mt = 0; mt < 4; mt++) {
        int row0 = m0 + wm + mt * 16 + g;
        #pragma unroll
        for (int nt = 0; nt < 4; nt++) {
            int col = n0 + wn + nt * 8 + tig * 2;
            float2 v0 = make_float2(acc[mt][nt][0], acc[mt][nt][1]);   // row0
            float2 v1 = make_float2(acc[mt][nt][2], acc[mt][nt][3]);   // row0+8
            if (HAS_BIAS) {
                float2 bb = *(const float2*)(bias + col);
                v0.x += bb.x; v0.y += bb.y; v1.x += bb.x; v1.y += bb.y;
            }
            if (HAS_RES) {
                float2 r0 = *(const float2*)(res + (size_t)row0 * N + col);
                float2 r1 = *(const float2*)(res + (size_t)(row0 + 8) * N + col);
                v0.x += r0.x; v0.y += r0.y; v1.x += r1.x; v1.y += r1.y;
            }
            *(float2*)(C + (size_t)row0 * N + col) = v0;
            *(float2*)(C + (size_t)(row0 + 8) * N + col) = v1;
        }
    }
}

// ---------------- QKV epilogue: type-emb add, RoPE, transpose to [B,H,T,HD] ----------------
__global__ void qkv_post_kernel(const float* __restrict__ qkv,
                                const int*   __restrict__ x_type,
                                const float* __restrict__ type_emb,
                                const float* __restrict__ seq_order,
                                float* __restrict__ Q, float* __restrict__ Ko,
                                float* __restrict__ V) {
    int row = blockIdx.x;       // b*T + t
    int b = row >> 10;
    int t = row & (T_ - 1);
    int p = threadIdx.x;        // 0..255 -> dim pair (2p, 2p+1)
    int d2 = 2 * p;

    int tq = x_type[b * (T_ + 1) + t];
    int tk = x_type[b * (T_ + 1) + t + 1];
    float pq = seq_order[b * (T_ + 1) + t];
    float pk = seq_order[b * (T_ + 1) + t + 1];

    const float* qr = qkv + (size_t)row * (3 * D_);
    float q0 = qr[d2]           + type_emb[(size_t)tq * (2 * D_) + d2];
    float q1 = qr[d2 + 1]       + type_emb[(size_t)tq * (2 * D_) + d2 + 1];
    float k0 = qr[D_ + d2]      + type_emb[(size_t)tk * (2 * D_) + D_ + d2];
    float k1 = qr[D_ + d2 + 1]  + type_emb[(size_t)tk * (2 * D_) + D_ + d2 + 1];
    float v0 = qr[2 * D_ + d2];
    float v1 = qr[2 * D_ + d2 + 1];

    int h  = d2 >> 6;
    int dl = d2 & 63;
    if (dl < DPR_) {
        // inv_freq = 10000^(-dl/32) = exp2(dl * -log2(10000)/32)
        float f = exp2f((float)dl * (-13.287712379549449f / 32.0f));
        float sq_, cq_, sk_, ck_;
        sincosf(pq * f, &sq_, &cq_);
        sincosf(pk * f, &sk_, &ck_);
        float nq0 = q0 * cq_ - q1 * sq_;
        float nq1 = q1 * cq_ + q0 * sq_;
        float nk0 = k0 * ck_ - k1 * sk_;
        float nk1 = k1 * ck_ + k0 * sk_;
        q0 = nq0; q1 = nq1; k0 = nk0; k1 = nk1;
    }
    size_t o = (((size_t)(b * H_ + h)) * T_ + t) * HD_ + dl;
    Q[o] = q0; Q[o + 1] = q1;
    Ko[o] = k0; Ko[o + 1] = k1;
    V[o] = v0; V[o + 1] = v1;
}

// ---------------- Flash attention (fp32, 1 query/thread, 64-key tiles) ----------------
// Load balance: block `pair` handles q-tiles {pair, 7-pair} -> every block does
// exactly 18 key-tiles; grid 256 = one balanced wave at 2 CTAs/SM.
__global__ __launch_bounds__(128)
void attn_kernel(const float* __restrict__ Q, const float* __restrict__ Kc,
                 const float* __restrict__ V, float* __restrict__ O) {
    constexpr int QT = 128, KT = 64;
    __shared__ float Ks[KT][HD_];
    __shared__ float Vs[KT][HD_];
    int pair = blockIdx.x;     // 0..3
    int h  = blockIdx.y;
    int b  = blockIdx.z;
    int tid = threadIdx.x;
    size_t head_base = ((size_t)(b * H_ + h)) * T_ * HD_;

    #pragma unroll 1
    for (int rep = 0; rep < 2; rep++) {
        int qt = (rep == 0) ? pair : (7 - pair);
        int q = qt * QT + tid;

        float qreg[HD_];
        {
            const float4* qp = (const float4*)(Q + head_base + (size_t)q * HD_);
            #pragma unroll
            for (int i = 0; i < 16; i++) {
                float4 tq = qp[i];
                qreg[4*i+0] = tq.x * 0.125f;
                qreg[4*i+1] = tq.y * 0.125f;
                qreg[4*i+2] = tq.z * 0.125f;
                qreg[4*i+3] = tq.w * 0.125f;
            }
        }
        float m = -1e30f, l = 0.f;
        float o[HD_];
        #pragma unroll
        for (int i = 0; i < HD_; i++) o[i] = 0.f;

        int nTiles = qt * 2 + 2;   // keys up to qt*128+127
        for (int kt = 0; kt < nTiles; kt++) {
            int j0 = kt * KT;
            const float4* kp = (const float4*)(Kc + head_base + (size_t)j0 * HD_);
            const float4* vp = (const float4*)(V  + head_base + (size_t)j0 * HD_);
            #pragma unroll
            for (int i = 0; i < 8; i++) {
                int idx = i * 128 + tid;
                ((float4*)Ks)[idx] = kp[idx];
                ((float4*)Vs)[idx] = vp[idx];
            }
            __syncthreads();

            for (int jc = 0; jc < KT; jc += 8) {
                if (j0 + jc > q) break;   // remaining keys all masked
                float s[8];
                #pragma unroll
                for (int jj = 0; jj < 8; jj++) {
                    const float4* krow = (const float4*)(&Ks[jc + jj][0]);
                    float a0 = 0.f, a1 = 0.f, a2 = 0.f, a3 = 0.f;
                    #pragma unroll
                    for (int i = 0; i < 16; i++) {
                        float4 kk = krow[i];
                        a0 += qreg[4*i+0] * kk.x;
                        a1 += qreg[4*i+1] * kk.y;
                        a2 += qreg[4*i+2] * kk.z;
                        a3 += qreg[4*i+3] * kk.w;
                    }
                    float sv = (a0 + a1) + (a2 + a3);
                    int j = j0 + jc + jj;
                    s[jj] = (j <= q) ? sv : -1e30f;
                }
                float cmax = s[0];
                #pragma unroll
                for (int jj = 1; jj < 8; jj++) cmax = fmaxf(cmax, s[jj]);
                if (cmax > m) {
                    float scale = __expf(m - cmax);
                    m = cmax;
                    l *= scale;
                    #pragma unroll
                    for (int i = 0; i < HD_; i++) o[i] *= scale;
                }
                #pragma unroll
                for (int jj = 0; jj < 8; jj++) {
                    float p = __expf(s[jj] - m);
                    l += p;
                    const float4* vrow = (const float4*)(&Vs[jc + jj][0]);
                    #pragma unroll
                    for (int i = 0; i < 16; i++) {
                        float4 vv = vrow[i];
                        o[4*i+0] += p * vv.x;
                        o[4*i+1] += p * vv.y;
                        o[4*i+2] += p * vv.z;
                        o[4*i+3] += p * vv.w;
                    }
                }
            }
            __syncthreads();
        }

        float inv = 1.0f / l;
        float4* op = (float4*)(O + head_base + (size_t)q * HD_);
        #pragma unroll
        for (int i = 0; i < 16; i++) {
            float4 v;
            v.x = o[4*i+0] * inv; v.y = o[4*i+1] * inv;
            v.z = o[4*i+2] * inv; v.w = o[4*i+3] * inv;
            op[i] = v;
        }
    }
}

// ---------------- SwiGLU: g = silu(z[:,DFF:]) * z[:,:DFF] ----------------
__global__ void swiglu_kernel(const float* __restrict__ z, float* __restrict__ g) {
    int idx = blockIdx.x * blockDim.x + threadIdx.x;   // over ROWS_*DFF_/4 float4
    int row = idx >> 8;          // 256 float4 per row
    int j4  = idx & 255;
    const float4* zr = (const float4*)(z + (size_t)row * (2 * DFF_));
    float4 a  = zr[j4];
    float4 gt = zr[j4 + DFF_ / 4];
    float4 r;
    r.x = a.x * (gt.x / (1.f + __expf(-gt.x)));
    r.y = a.y * (gt.y / (1.f + __expf(-gt.y)));
    r.z = a.z * (gt.z / (1.f + __expf(-gt.z)));
    r.w = a.w * (gt.w / (1.f + __expf(-gt.w)));
    ((float4*)(g + (size_t)row * DFF_))[j4] = r;
}

// ---------------- launch ----------------
extern "C" void kernel_launch(void* const* d_in, const int* in_sizes, int n_in,
                              void* d_out, int out_size) {
    (void)in_sizes; (void)n_in; (void)out_size;
    const int*   x_type   = (const int*)  d_in[0];
    const float* x_value  = (const float*)d_in[1];
    const float* seq_ord  = (const float*)d_in[2];
    const float* W_attn   = (const float*)d_in[3];
    const float* type_emb = (const float*)d_in[4];
    const float* ln1_g    = (const float*)d_in[5];
    const float* ln1_b    = (const float*)d_in[6];
    const float* ln2_g    = (const float*)d_in[7];
    const float* ln2_b    = (const float*)d_in[8];
    const float* W1       = (const float*)d_in[9];
    const float* b1       = (const float*)d_in[10];
    const float* W2       = (const float*)d_in[11];
    const float* b2       = (const float*)d_in[12];
    float* out = (float*)d_out;

    float *p_h, *p_qkv, *p_q, *p_k, *p_v, *p_ao, *p_xres, *p_h2, *p_z, *p_g;
    cudaGetSymbolAddress((void**)&p_h,    g_h);
    cudaGetSymbolAddress((void**)&p_qkv,  g_qkv);
    cudaGetSymbolAddress((void**)&p_q,    g_q);
    cudaGetSymbolAddress((void**)&p_k,    g_k);
    cudaGetSymbolAddress((void**)&p_v,    g_v);
    cudaGetSymbolAddress((void**)&p_ao,   g_ao);
    cudaGetSymbolAddress((void**)&p_xres, g_xres);
    cudaGetSymbolAddress((void**)&p_h2,   g_h2);
    cudaGetSymbolAddress((void**)&p_z,    g_z);
    cudaGetSymbolAddress((void**)&p_g,    g_g);

    cudaFuncSetAttribute(tf32_gemm<false, false>,
                         cudaFuncAttributeMaxDynamicSharedMemorySize, GSMEM_BYTES);
    cudaFuncSetAttribute(tf32_gemm<true, false>,
                         cudaFuncAttributeMaxDynamicSharedMemorySize, GSMEM_BYTES);
    cudaFuncSetAttribute(tf32_gemm<true, true>,
                         cudaFuncAttributeMaxDynamicSharedMemorySize, GSMEM_BYTES);

    // 1. LN1
    ln_kernel<<<ROWS_, 128>>>(x_value, ln1_g, ln1_b, p_h);
    // 2. QKV GEMM: [8192,512] @ [512,1536]
    tf32_gemm<false, false><<<dim3(1536 / 128, ROWS_ / 128), 256, GSMEM_BYTES>>>(
        p_h, W_attn, nullptr, nullptr, p_qkv, ROWS_, 3 * D_, D_);
    // 3. emb + RoPE + transpose
    qkv_post_kernel<<<ROWS_, 256>>>(p_qkv, x_type, type_emb, seq_ord, p_q, p_k, p_v);
    // 4. causal flash attention (balanced q-tile pairs)
    attn_kernel<<<dim3(4, H_, B_), 128>>>(p_q, p_k, p_v, p_ao);
    // 5. residual + LN2
    addres_ln2_kernel<<<ROWS_, 128>>>(x_value, p_ao, ln2_g, ln2_b, p_xres, p_h2);
    // 6. FFN GEMM1: [8192,512] @ [512,2048] + b1
    tf32_gemm<true, false><<<dim3(2 * DFF_ / 128, ROWS_ / 128), 256, GSMEM_BYTES>>>(
        p_h2, W1, b1, nullptr, p_z, ROWS_, 2 * DFF_, D_);
    // 7. SwiGLU
    swiglu_kernel<<<(ROWS_ * DFF_ / 4) / 256, 256>>>(p_z, p_g);
    // 8. FFN GEMM2: [8192,1024] @ [1024,512] + b2 + residual -> out
    tf32_gemm<true, true><<<dim3(D_ / 128, ROWS_ / 128), 256, GSMEM_BYTES>>>(
        p_g, W2, b2, p_xres, out, ROWS_, D_, DFF_);
}

// round 5
// speedup vs baseline: 3.4564x; 1.5780x over previous
#include <cuda_runtime.h>
#include <cuda_bf16.h>
#include <math.h>

// Problem constants
#define B_  8
#define T_  1024
#define D_  512
#define H_  8
#define HD_ 64
#define DFF_ 1024
#define DPR_ 32
#define ROWS_ (B_*T_)   // 8192

// ---------------- scratch (device globals; no allocation allowed) ----------------
__device__ float g_h   [ROWS_*D_];        // ln1 output
__device__ float g_qkv [ROWS_*3*D_];      // qkv projection
__device__ float g_q   [B_*H_*T_*HD_];    // [B,H,T,HD]
__device__ float g_k   [B_*H_*T_*HD_];
__device__ float g_v   [B_*H_*T_*HD_];
__device__ float g_ao  [B_*H_*T_*HD_];    // attention out [B,H,T,HD]
__device__ float g_xres[ROWS_*D_];        // x_value + attn
__device__ float g_h2  [ROWS_*D_];        // ln2 output
__device__ float g_z   [ROWS_*2*DFF_];    // ffn1 raw
__device__ float g_g   [ROWS_*DFF_];      // swiglu output

// ---------------- helpers ----------------
__device__ __forceinline__ void cpasync16(unsigned s, const void* g) {
    asm volatile("cp.async.cg.shared.global [%0], [%1], 16;" :: "r"(s), "l"(g));
}
__device__ __forceinline__ void cpcommit() {
    asm volatile("cp.async.commit_group;");
}
__device__ __forceinline__ unsigned rna_tf32(unsigned u) {
    unsigned r;
    asm("cvt.rna.tf32.f32 %0, %1;" : "=r"(r) : "r"(u));
    return r;
}
__device__ __forceinline__ unsigned rna_tf32f(float f) {
    unsigned r;
    asm("cvt.rna.tf32.f32 %0, %1;" : "=r"(r) : "f"(f));
    return r;
}
__device__ __forceinline__ void mma_tf32(float& c0, float& c1, float& c2, float& c3,
                                         unsigned a0, unsigned a1, unsigned a2, unsigned a3,
                                         unsigned b0, unsigned b1) {
    asm volatile(
        "mma.sync.aligned.m16n8k8.row.col.f32.tf32.tf32.f32 "
        "{%0,%1,%2,%3}, {%4,%5,%6,%7}, {%8,%9}, {%0,%1,%2,%3};"
        : "+f"(c0), "+f"(c1), "+f"(c2), "+f"(c3)
        : "r"(a0), "r"(a1), "r"(a2), "r"(a3), "r"(b0), "r"(b1));
}

__device__ __forceinline__ void blockReduce2_128(float& a, float& b) {
    #pragma unroll
    for (int o = 16; o > 0; o >>= 1) {
        a += __shfl_xor_sync(0xffffffffu, a, o);
        b += __shfl_xor_sync(0xffffffffu, b, o);
    }
    __shared__ float sa[4], sb[4];
    int w = threadIdx.x >> 5;
    if ((threadIdx.x & 31) == 0) { sa[w] = a; sb[w] = b; }
    __syncthreads();
    a = sa[0] + sa[1] + sa[2] + sa[3];
    b = sb[0] + sb[1] + sb[2] + sb[3];
}

// ---------------- LayerNorm (row = 512 floats, 128 threads, float4) ----------------
__global__ void ln_kernel(const float* __restrict__ x,
                          const float* __restrict__ g,
                          const float* __restrict__ bta,
                          float* __restrict__ out) {
    int row = blockIdx.x;
    int tid = threadIdx.x;
    const float4* xr = (const float4*)(x + (size_t)row * D_);
    float4 v = xr[tid];
    float s  = v.x + v.y + v.z + v.w;
    float sq = v.x*v.x + v.y*v.y + v.z*v.z + v.w*v.w;
    blockReduce2_128(s, sq);
    float mean = s * (1.0f / D_);
    float var  = sq * (1.0f / D_) - mean * mean;
    float inv  = rsqrtf(var + 1e-5f);
    float4 gg = ((const float4*)g)[tid];
    float4 bb = ((const float4*)bta)[tid];
    float4 o;
    o.x = (v.x - mean) * inv * gg.x + bb.x;
    o.y = (v.y - mean) * inv * gg.y + bb.y;
    o.z = (v.z - mean) * inv * gg.z + bb.z;
    o.w = (v.w - mean) * inv * gg.w + bb.w;
    ((float4*)(out + (size_t)row * D_))[tid] = o;
}

// ---------------- residual add + LayerNorm2 (gathers heads) ----------------
__global__ void addres_ln2_kernel(const float* __restrict__ xv,
                                  const float* __restrict__ ao,
                                  const float* __restrict__ g,
                                  const float* __restrict__ bta,
                                  float* __restrict__ xres,
                                  float* __restrict__ h2) {
    int row = blockIdx.x;          // b*T + t
    int b = row >> 10;
    int t = row & (T_ - 1);
    int tid = threadIdx.x;         // 0..127, handles dims 4*tid..4*tid+3
    int d  = tid * 4;
    int h  = d >> 6;
    int dl = d & 63;
    float4 a = *(const float4*)(ao + ((((size_t)(b * H_ + h)) * T_ + t) * HD_ + dl));
    float4 v = ((const float4*)(xv + (size_t)row * D_))[tid];
    v.x += a.x; v.y += a.y; v.z += a.z; v.w += a.w;
    ((float4*)(xres + (size_t)row * D_))[tid] = v;
    float s  = v.x + v.y + v.z + v.w;
    float sq = v.x*v.x + v.y*v.y + v.z*v.z + v.w*v.w;
    blockReduce2_128(s, sq);
    float mean = s * (1.0f / D_);
    float var  = sq * (1.0f / D_) - mean * mean;
    float inv  = rsqrtf(var + 1e-5f);
    float4 gg = ((const float4*)g)[tid];
    float4 bb = ((const float4*)bta)[tid];
    float4 o;
    o.x = (v.x - mean) * inv * gg.x + bb.x;
    o.y = (v.y - mean) * inv * gg.y + bb.y;
    o.z = (v.z - mean) * inv * gg.z + bb.z;
    o.w = (v.w - mean) * inv * gg.w + bb.w;
    ((float4*)(h2 + (size_t)row * D_))[tid] = o;
}

// ================= tf32 tensor-core GEMM (cp.async, conflict-free pads) ========
#define ASTRIDE 36
#define BSTRIDE 136
#define STAGE_WORDS (128*ASTRIDE + 32*BSTRIDE)   // 8960
#define GSMEM_BYTES (2 * STAGE_WORDS * 4)        // 71680

template<bool HAS_BIAS, bool HAS_RES>
__global__ __launch_bounds__(256, 2)
void tf32_gemm(const float* __restrict__ A, const float* __restrict__ Bm,
               const float* __restrict__ bias, const float* __restrict__ res,
               float* __restrict__ C, int M, int N, int K) {
    extern __shared__ float smem[];
    const unsigned sbase = (unsigned)__cvta_generic_to_shared(smem);
    const int t = threadIdx.x;
    const int m0 = blockIdx.y * 128;
    const int n0 = blockIdx.x * 128;
    const int warp = t >> 5, lane = t & 31;
    const int wm = (warp >> 2) * 64;
    const int wn = (warp & 3) * 32;
    const int g  = lane >> 2, tig = lane & 3;

    float acc[4][4][4];
    #pragma unroll
    for (int i = 0; i < 4; i++)
        #pragma unroll
        for (int j = 0; j < 4; j++)
            #pragma unroll
            for (int e = 0; e < 4; e++) acc[i][j][e] = 0.f;

    const int mA = t >> 3, k4 = t & 7;
    const int kB = t >> 5, n4 = t & 31;

    {
        unsigned sA = sbase;
        unsigned sB = sbase + 128*ASTRIDE*4;
        #pragma unroll
        for (int j = 0; j < 4; j++) {
            int ma = mA + 32*j;
            cpasync16(sA + (ma*ASTRIDE + k4*4)*4, A + (size_t)(m0 + ma)*K + k4*4);
            int kb = kB + 8*j;
            cpasync16(sB + (kb*BSTRIDE + n4*4)*4, Bm + (size_t)kb*N + n0 + n4*4);
        }
        cpcommit();
    }

    const int nIter = K >> 5;
    int buf = 0;
    for (int it = 0; it < nIter; ++it) {
        if (it + 1 < nIter) {
            int k0 = (it + 1) << 5;
            unsigned sA = sbase + (buf ^ 1) * STAGE_WORDS * 4;
            unsigned sB = sA + 128*ASTRIDE*4;
            #pragma unroll
            for (int j = 0; j < 4; j++) {
                int ma = mA + 32*j;
                cpasync16(sA + (ma*ASTRIDE + k4*4)*4,
                          A + (size_t)(m0 + ma)*K + k0 + k4*4);
                int kb = kB + 8*j;
                cpasync16(sB + (kb*BSTRIDE + n4*4)*4,
                          Bm + (size_t)(k0 + kb)*N + n0 + n4*4);
            }
            cpcommit();
            asm volatile("cp.async.wait_group 1;");
        } else {
            asm volatile("cp.async.wait_group 0;");
        }
        __syncthreads();

        const unsigned* Asu = (const unsigned*)(smem + buf * STAGE_WORDS);
        const unsigned* Bsu = Asu + 128*ASTRIDE;

        #pragma unroll
        for (int ks = 0; ks < 4; ks++) {
            unsigned a[4][2][2], b[4][2];
            #pragma unroll
            for (int mt = 0; mt < 4; mt++) {
                const unsigned* p = Asu + (wm + mt*16 + g)*ASTRIDE + ks*8 + tig;
                a[mt][0][0] = rna_tf32(p[0]);
                a[mt][1][0] = rna_tf32(p[8*ASTRIDE]);
                a[mt][0][1] = rna_tf32(p[4]);
                a[mt][1][1] = rna_tf32(p[8*ASTRIDE + 4]);
            }
            #pragma unroll
            for (int nt = 0; nt < 4; nt++) {
                const unsigned* p = Bsu + (ks*8 + (lane&3))*BSTRIDE
                                        + wn + nt*8 + (lane>>2);
                b[nt][0] = rna_tf32(p[0]);
                b[nt][1] = rna_tf32(p[4*BSTRIDE]);
            }
            #pragma unroll
            for (int mt = 0; mt < 4; mt++)
                #pragma unroll
                for (int nt = 0; nt < 4; nt++)
                    mma_tf32(acc[mt][nt][0], acc[mt][nt][1],
                             acc[mt][nt][2], acc[mt][nt][3],
                             a[mt][0][0], a[mt][1][0], a[mt][0][1], a[mt][1][1],
                             b[nt][0], b[nt][1]);
        }
        __syncthreads();
        buf ^= 1;
    }

    #pragma unroll
    for (int mt = 0; mt < 4; mt++) {
        int row0 = m0 + wm + mt * 16 + g;
        #pragma unroll
        for (int nt = 0; nt < 4; nt++) {
            int col = n0 + wn + nt * 8 + tig * 2;
            float2 v0 = make_float2(acc[mt][nt][0], acc[mt][nt][1]);
            float2 v1 = make_float2(acc[mt][nt][2], acc[mt][nt][3]);
            if (HAS_BIAS) {
                float2 bb = *(const float2*)(bias + col);
                v0.x += bb.x; v0.y += bb.y; v1.x += bb.x; v1.y += bb.y;
            }
            if (HAS_RES) {
                float2 r0 = *(const float2*)(res + (size_t)row0 * N + col);
                float2 r1 = *(const float2*)(res + (size_t)(row0 + 8) * N + col);
                v0.x += r0.x; v0.y += r0.y; v1.x += r1.x; v1.y += r1.y;
            }
            *(float2*)(C + (size_t)row0 * N + col) = v0;
            *(float2*)(C + (size_t)(row0 + 8) * N + col) = v1;
        }
    }
}

// ---------------- QKV epilogue: type-emb add, RoPE, transpose to [B,H,T,HD] ----------------
__global__ void qkv_post_kernel(const float* __restrict__ qkv,
                                const int*   __restrict__ x_type,
                                const float* __restrict__ type_emb,
                                const float* __restrict__ seq_order,
                                float* __restrict__ Q, float* __restrict__ Ko,
                                float* __restrict__ V) {
    int row = blockIdx.x;       // b*T + t
    int b = row >> 10;
    int t = row & (T_ - 1);
    int p = threadIdx.x;        // 0..255 -> dim pair (2p, 2p+1)
    int d2 = 2 * p;

    int tq = x_type[b * (T_ + 1) + t];
    int tk = x_type[b * (T_ + 1) + t + 1];
    float pq = seq_order[b * (T_ + 1) + t];
    float pk = seq_order[b * (T_ + 1) + t + 1];

    const float* qr = qkv + (size_t)row * (3 * D_);
    float q0 = qr[d2]           + type_emb[(size_t)tq * (2 * D_) + d2];
    float q1 = qr[d2 + 1]       + type_emb[(size_t)tq * (2 * D_) + d2 + 1];
    float k0 = qr[D_ + d2]      + type_emb[(size_t)tk * (2 * D_) + D_ + d2];
    float k1 = qr[D_ + d2 + 1]  + type_emb[(size_t)tk * (2 * D_) + D_ + d2 + 1];
    float v0 = qr[2 * D_ + d2];
    float v1 = qr[2 * D_ + d2 + 1];

    int h  = d2 >> 6;
    int dl = d2 & 63;
    if (dl < DPR_) {
        float f = exp2f((float)dl * (-13.287712379549449f / 32.0f));
        float sq_, cq_, sk_, ck_;
        sincosf(pq * f, &sq_, &cq_);
        sincosf(pk * f, &sk_, &ck_);
        float nq0 = q0 * cq_ - q1 * sq_;
        float nq1 = q1 * cq_ + q0 * sq_;
        float nk0 = k0 * ck_ - k1 * sk_;
        float nk1 = k1 * ck_ + k0 * sk_;
        q0 = nq0; q1 = nq1; k0 = nk0; k1 = nk1;
    }
    size_t o = (((size_t)(b * H_ + h)) * T_ + t) * HD_ + dl;
    Q[o] = q0; Q[o + 1] = q1;
    Ko[o] = k0; Ko[o + 1] = k1;
    V[o] = v0; V[o + 1] = v1;
}

// ============== tf32 tensor-core flash attention ==============
// CTA: 256 thr / 8 warps; Q-tile 128 rows (16/warp), K-tile 64 keys.
// K,V double-buffered via cp.async in smem rows padded to 68 words.
// S = Q@K^T via m16n8k8; online softmax on C-frags; P C->A frag via warp
// shuffles; O += P@V via m16n8k8.  Balanced q-tile pairs (18 tiles/CTA).
#define AT_PAD 68
#define AT_STAGE (2*64*AT_PAD)              // K + V, words per stage
#define AT_SMEM (2*AT_STAGE*4)              // 69632 bytes

__global__ __launch_bounds__(256, 2)
void attn_tc_kernel(const float* __restrict__ Q, const float* __restrict__ Kc,
                    const float* __restrict__ V, float* __restrict__ O) {
    extern __shared__ float sm[];
    const unsigned sbase = (unsigned)__cvta_generic_to_shared(sm);
    const int pair = blockIdx.x;       // 0..3
    const int h  = blockIdx.y;
    const int b  = blockIdx.z;
    const int t = threadIdx.x;
    const int warp = t >> 5, lane = t & 31;
    const int g = lane >> 2, tig = lane & 3;
    const int wm = warp * 16;
    const size_t hb = ((size_t)(b * H_ + h)) * T_ * HD_;

    // copy coords: each thread does 4 K + 4 V cp.async per tile
    const int cr = t >> 4;            // rows t>>4 + 16*j
    const int cc4 = (t & 15) * 4;

    #pragma unroll 1
    for (int rep = 0; rep < 2; rep++) {
        const int qt = (rep == 0) ? pair : (7 - pair);
        const int qbase = qt * 128;

        // ---- Q fragments (scaled by 1/8, tf32) ----
        unsigned qa[8][4];
        {
            const float* Qp = Q + hb + (size_t)(qbase + wm) * HD_;
            #pragma unroll
            for (int ks = 0; ks < 8; ks++) {
                int c0 = ks * 8 + tig;
                qa[ks][0] = rna_tf32f(Qp[g * 64 + c0] * 0.125f);
                qa[ks][1] = rna_tf32f(Qp[(g + 8) * 64 + c0] * 0.125f);
                qa[ks][2] = rna_tf32f(Qp[g * 64 + c0 + 4] * 0.125f);
                qa[ks][3] = rna_tf32f(Qp[(g + 8) * 64 + c0 + 4] * 0.125f);
            }
        }

        float m0 = -1e30f, m1 = -1e30f, l0 = 0.f, l1 = 0.f;
        float o[8][4];
        #pragma unroll
        for (int nt = 0; nt < 8; nt++)
            #pragma unroll
            for (int e = 0; e < 4; e++) o[nt][e] = 0.f;

        const int nT = qt * 2 + 2;

        // prefetch tile 0 into buf 0
        {
            unsigned sK = sbase;
            unsigned sV = sK + 64 * AT_PAD * 4;
            const float* kp = Kc + hb;
            const float* vp = V + hb;
            #pragma unroll
            for (int j = 0; j < 4; j++) {
                int r = cr + 16 * j;
                cpasync16(sK + (r * AT_PAD + cc4) * 4, kp + r * 64 + cc4);
                cpasync16(sV + (r * AT_PAD + cc4) * 4, vp + r * 64 + cc4);
            }
            cpcommit();
        }

        int buf = 0;
        for (int kt = 0; kt < nT; kt++) {
            const int j0 = kt * 64;
            if (kt + 1 < nT) {
                unsigned sK = sbase + (buf ^ 1) * AT_STAGE * 4;
                unsigned sV = sK + 64 * AT_PAD * 4;
                const float* kp = Kc + hb + (size_t)(j0 + 64) * 64;
                const float* vp = V + hb + (size_t)(j0 + 64) * 64;
                #pragma unroll
                for (int j = 0; j < 4; j++) {
                    int r = cr + 16 * j;
                    cpasync16(sK + (r * AT_PAD + cc4) * 4, kp + r * 64 + cc4);
                    cpasync16(sV + (r * AT_PAD + cc4) * 4, vp + r * 64 + cc4);
                }
                cpcommit();
                asm volatile("cp.async.wait_group 1;");
            } else {
                asm volatile("cp.async.wait_group 0;");
            }
            __syncthreads();

            if (j0 <= qbase + wm + 15) {   // warp has unmasked keys in this tile
                const unsigned* Ksmu = (const unsigned*)(sm + buf * AT_STAGE);
                const unsigned* Vsmu = Ksmu + 64 * AT_PAD;

                // ---- S = Q @ K^T  (16 x 64 per warp) ----
                float s[8][4];
                #pragma unroll
                for (int nt = 0; nt < 8; nt++) {
                    float c0 = 0.f, c1 = 0.f, c2 = 0.f, c3 = 0.f;
                    const unsigned* kp = Ksmu + (nt * 8 + g) * AT_PAD + tig;
                    #pragma unroll
                    for (int ks = 0; ks < 8; ks++) {
                        unsigned b0 = rna_tf32(kp[ks * 8]);
                        unsigned b1 = rna_tf32(kp[ks * 8 + 4]);
                        mma_tf32(c0, c1, c2, c3,
                                 qa[ks][0], qa[ks][1], qa[ks][2], qa[ks][3],
                                 b0, b1);
                    }
                    s[nt][0] = c0; s[nt][1] = c1; s[nt][2] = c2; s[nt][3] = c3;
                }

                // ---- causal mask (only needed near diagonal) ----
                const int r0 = qbase + wm + g, r1 = r0 + 8;
                if (j0 + 63 > qbase + wm) {
                    #pragma unroll
                    for (int nt = 0; nt < 8; nt++) {
                        int col = j0 + nt * 8 + 2 * tig;
                        if (col > r0)     s[nt][0] = -1e30f;
                        if (col + 1 > r0) s[nt][1] = -1e30f;
                        if (col > r1)     s[nt][2] = -1e30f;
                        if (col + 1 > r1) s[nt][3] = -1e30f;
                    }
                }

                // ---- online softmax ----
                float mx0 = -1e30f, mx1 = -1e30f;
                #pragma unroll
                for (int nt = 0; nt < 8; nt++) {
                    mx0 = fmaxf(mx0, fmaxf(s[nt][0], s[nt][1]));
                    mx1 = fmaxf(mx1, fmaxf(s[nt][2], s[nt][3]));
                }
                mx0 = fmaxf(mx0, __shfl_xor_sync(0xffffffffu, mx0, 1));
                mx0 = fmaxf(mx0, __shfl_xor_sync(0xffffffffu, mx0, 2));
                mx1 = fmaxf(mx1, __shfl_xor_sync(0xffffffffu, mx1, 1));
                mx1 = fmaxf(mx1, __shfl_xor_sync(0xffffffffu, mx1, 2));
                float nm0 = fmaxf(m0, mx0), nm1 = fmaxf(m1, mx1);
                float sc0 = __expf(m0 - nm0), sc1 = __expf(m1 - nm1);
                m0 = nm0; m1 = nm1;
                float sum0 = 0.f, sum1 = 0.f;
                #pragma unroll
                for (int nt = 0; nt < 8; nt++) {
                    s[nt][0] = __expf(s[nt][0] - m0); sum0 += s[nt][0];
                    s[nt][1] = __expf(s[nt][1] - m0); sum0 += s[nt][1];
                    s[nt][2] = __expf(s[nt][2] - m1); sum1 += s[nt][2];
                    s[nt][3] = __expf(s[nt][3] - m1); sum1 += s[nt][3];
                }
                l0 = l0 * sc0 + sum0;        // per-thread partial over its 16 cols
                l1 = l1 * sc1 + sum1;
                #pragma unroll
                for (int nt = 0; nt < 8; nt++) {
                    o[nt][0] *= sc0; o[nt][1] *= sc0;
                    o[nt][2] *= sc1; o[nt][3] *= sc1;
                }

                // ---- O += P @ V  (P C-frag -> A-frag via warp shuffles) ----
                #pragma unroll
                for (int ks = 0; ks < 8; ks++) {
                    const int srcA = (lane & 0x1c) | (tig >> 1);
                    float v00 = __shfl_sync(0xffffffffu, s[ks][0], srcA);
                    float v01 = __shfl_sync(0xffffffffu, s[ks][1], srcA);
                    float a0f = (tig & 1) ? v01 : v00;
                    float v02 = __shfl_sync(0xffffffffu, s[ks][0], srcA + 2);
                    float v03 = __shfl_sync(0xffffffffu, s[ks][1], srcA + 2);
                    float a2f = (tig & 1) ? v03 : v02;
                    float w00 = __shfl_sync(0xffffffffu, s[ks][2], srcA);
                    float w01 = __shfl_sync(0xffffffffu, s[ks][3], srcA);
                    float a1f = (tig & 1) ? w01 : w00;
                    float w02 = __shfl_sync(0xffffffffu, s[ks][2], srcA + 2);
                    float w03 = __shfl_sync(0xffffffffu, s[ks][3], srcA + 2);
                    float a3f = (tig & 1) ? w03 : w02;
                    unsigned a0 = rna_tf32f(a0f), a1 = rna_tf32f(a1f);
                    unsigned a2 = rna_tf32f(a2f), a3 = rna_tf32f(a3f);
                    const unsigned* vp = Vsmu + (ks * 8 + tig) * AT_PAD + g;
                    #pragma unroll
                    for (int nt = 0; nt < 8; nt++) {
                        unsigned b0 = rna_tf32(vp[nt * 8]);
                        unsigned b1 = rna_tf32(vp[4 * AT_PAD + nt * 8]);
                        mma_tf32(o[nt][0], o[nt][1], o[nt][2], o[nt][3],
                                 a0, a1, a2, a3, b0, b1);
                    }
                }
            }
            __syncthreads();
            buf ^= 1;
        }

        // ---- epilogue: reduce l over tig lanes, normalize, store ----
        l0 += __shfl_xor_sync(0xffffffffu, l0, 1);
        l0 += __shfl_xor_sync(0xffffffffu, l0, 2);
        l1 += __shfl_xor_sync(0xffffffffu, l1, 1);
        l1 += __shfl_xor_sync(0xffffffffu, l1, 2);
        float inv0 = 1.0f / l0, inv1 = 1.0f / l1;
        float* Op = O + hb + (size_t)(qbase + wm) * HD_;
        #pragma unroll
        for (int nt = 0; nt < 8; nt++) {
            int col = nt * 8 + 2 * tig;
            *(float2*)(Op + g * 64 + col) =
                make_float2(o[nt][0] * inv0, o[nt][1] * inv0);
            *(float2*)(Op + (g + 8) * 64 + col) =
                make_float2(o[nt][2] * inv1, o[nt][3] * inv1);
        }
    }
}

// ---------------- SwiGLU: g = silu(z[:,DFF:]) * z[:,:DFF] ----------------
__global__ void swiglu_kernel(const float* __restrict__ z, float* __restrict__ g) {
    int idx = blockIdx.x * blockDim.x + threadIdx.x;
    int row = idx >> 8;
    int j4  = idx & 255;
    const float4* zr = (const float4*)(z + (size_t)row * (2 * DFF_));
    float4 a  = zr[j4];
    float4 gt = zr[j4 + DFF_ / 4];
    float4 r;
    r.x = a.x * (gt.x / (1.f + __expf(-gt.x)));
    r.y = a.y * (gt.y / (1.f + __expf(-gt.y)));
    r.z = a.z * (gt.z / (1.f + __expf(-gt.z)));
    r.w = a.w * (gt.w / (1.f + __expf(-gt.w)));
    ((float4*)(g + (size_t)row * DFF_))[j4] = r;
}

// ---------------- launch ----------------
extern "C" void kernel_launch(void* const* d_in, const int* in_sizes, int n_in,
                              void* d_out, int out_size) {
    (void)in_sizes; (void)n_in; (void)out_size;
    const int*   x_type   = (const int*)  d_in[0];
    const float* x_value  = (const float*)d_in[1];
    const float* seq_ord  = (const float*)d_in[2];
    const float* W_attn   = (const float*)d_in[3];
    const float* type_emb = (const float*)d_in[4];
    const float* ln1_g    = (const float*)d_in[5];
    const float* ln1_b    = (const float*)d_in[6];
    const float* ln2_g    = (const float*)d_in[7];
    const float* ln2_b    = (const float*)d_in[8];
    const float* W1       = (const float*)d_in[9];
    const float* b1       = (const float*)d_in[10];
    const float* W2       = (const float*)d_in[11];
    const float* b2       = (const float*)d_in[12];
    float* out = (float*)d_out;

    float *p_h, *p_qkv, *p_q, *p_k, *p_v, *p_ao, *p_xres, *p_h2, *p_z, *p_g;
    cudaGetSymbolAddress((void**)&p_h,    g_h);
    cudaGetSymbolAddress((void**)&p_qkv,  g_qkv);
    cudaGetSymbolAddress((void**)&p_q,    g_q);
    cudaGetSymbolAddress((void**)&p_k,    g_k);
    cudaGetSymbolAddress((void**)&p_v,    g_v);
    cudaGetSymbolAddress((void**)&p_ao,   g_ao);
    cudaGetSymbolAddress((void**)&p_xres, g_xres);
    cudaGetSymbolAddress((void**)&p_h2,   g_h2);
    cudaGetSymbolAddress((void**)&p_z,    g_z);
    cudaGetSymbolAddress((void**)&p_g,    g_g);

    cudaFuncSetAttribute(tf32_gemm<false, false>,
                         cudaFuncAttributeMaxDynamicSharedMemorySize, GSMEM_BYTES);
    cudaFuncSetAttribute(tf32_gemm<true, false>,
                         cudaFuncAttributeMaxDynamicSharedMemorySize, GSMEM_BYTES);
    cudaFuncSetAttribute(tf32_gemm<true, true>,
                         cudaFuncAttributeMaxDynamicSharedMemorySize, GSMEM_BYTES);
    cudaFuncSetAttribute(attn_tc_kernel,
                         cudaFuncAttributeMaxDynamicSharedMemorySize, AT_SMEM);

    // 1. LN1
    ln_kernel<<<ROWS_, 128>>>(x_value, ln1_g, ln1_b, p_h);
    // 2. QKV GEMM: [8192,512] @ [512,1536]
    tf32_gemm<false, false><<<dim3(1536 / 128, ROWS_ / 128), 256, GSMEM_BYTES>>>(
        p_h, W_attn, nullptr, nullptr, p_qkv, ROWS_, 3 * D_, D_);
    // 3. emb + RoPE + transpose
    qkv_post_kernel<<<ROWS_, 256>>>(p_qkv, x_type, type_emb, seq_ord, p_q, p_k, p_v);
    // 4. causal flash attention (tensor cores, balanced q-tile pairs)
    attn_tc_kernel<<<dim3(4, H_, B_), 256, AT_SMEM>>>(p_q, p_k, p_v, p_ao);
    // 5. residual + LN2
    addres_ln2_kernel<<<ROWS_, 128>>>(x_value, p_ao, ln2_g, ln2_b, p_xres, p_h2);
    // 6. FFN GEMM1: [8192,512] @ [512,2048] + b1
    tf32_gemm<true, false><<<dim3(2 * DFF_ / 128, ROWS_ / 128), 256, GSMEM_BYTES>>>(
        p_h2, W1, b1, nullptr, p_z, ROWS_, 2 * DFF_, D_);
    // 7. SwiGLU
    swiglu_kernel<<<(ROWS_ * DFF_ / 4) / 256, 256>>>(p_z, p_g);
    // 8. FFN GEMM2: [8192,1024] @ [1024,512] + b2 + residual -> out
    tf32_gemm<true, true><<<dim3(D_ / 128, ROWS_ / 128), 256, GSMEM_BYTES>>>(
        p_g, W2, b2, p_xres, out, ROWS_, D_, DFF_);
}